// round 3
// baseline (speedup 1.0000x reference)
#include <cuda_runtime.h>
#include <math.h>

#define NN 100000
#define EE 640000
#define BB 2000
#define ND 256
#define ED 128
#define EMBD 256
#define LBLK 3

// ------------------------- scratch (no allocations allowed) -------------------------
__device__ float g_hn0[NN * ND];
__device__ float g_hn1[NN * ND];
__device__ float g_he0[EE * ED];
__device__ float g_he1[EE * ED];
__device__ float g_agg[NN * ND];
__device__ float g_dist[EE];
__device__ int   g_src[EE];
__device__ int   g_dst[EE];
__device__ int   g_bn[NN];
__device__ int   g_be[EE];
__device__ int   g_is64;
__device__ float g_sum_n[BB * ND];
__device__ float g_sum_e[BB * ED];
__device__ float g_cnt_n[BB];
__device__ float g_cnt_e[BB];
__device__ float g_hsub[BB * (ND + ED)];
__device__ float g_h1[BB * 2 * EMBD];

// ------------------------- dtype detection (int32 vs int64 indices) -------------------------
// int64 values < 2^32 have all-zero odd 32-bit words; random int32 node ids don't.
__global__ void k_detect(const unsigned int* __restrict__ u) {
    if (threadIdx.x != 0 || blockIdx.x != 0) return;
    int odd_nonzero = 0;
    for (int i = 0; i < 64; i++)
        if (u[2 * i + 1] != 0u) odd_nonzero++;
    g_is64 = (odd_nonzero == 0) ? 1 : 0;
}

__global__ void k_cvt(const void* __restrict__ p, int n, int* __restrict__ outp) {
    int i = blockIdx.x * 256 + threadIdx.x;
    if (i >= n) return;
    if (g_is64) outp[i] = (int)((const long long*)p)[i];
    else        outp[i] = ((const int*)p)[i];
}

// ------------------------- prep: edge distance -------------------------
__global__ void k_prep_edge(const float* __restrict__ pos) {
    int e = blockIdx.x * 256 + threadIdx.x;
    if (e >= EE) return;
    int s = g_src[e];
    int d = g_dst[e];
    float dx = pos[d * 3 + 0] - pos[s * 3 + 0];
    float dy = pos[d * 3 + 1] - pos[s * 3 + 1];
    float dz = pos[d * 3 + 2] - pos[s * 3 + 2];
    g_dist[e] = sqrtf(dx * dx + dy * dy + dz * dz);
}

// ------------------------- node/edge type embedding -------------------------
__global__ void k_embed_node(const float* __restrict__ hfeat,
                             const float* __restrict__ W,
                             float* __restrict__ outp) {
    __shared__ float sw[16 * 256];
    for (int i = threadIdx.x; i < 16 * 256; i += 256) sw[i] = W[i];
    __syncthreads();
    int c = threadIdx.x;
    int n0 = blockIdx.x * 8;
    for (int r = 0; r < 8; r++) {
        int n = n0 + r;
        if (n >= NN) return;
        float acc = 0.f;
#pragma unroll
        for (int k = 0; k < 16; k++) acc += hfeat[n * 16 + k] * sw[k * 256 + c];
        outp[n * 256 + c] = acc;
    }
}

__global__ void k_embed_edge(const float* __restrict__ hfeat,
                             const float* __restrict__ W,
                             float* __restrict__ outp) {
    __shared__ float sw[5 * 128];
    for (int i = threadIdx.x; i < 5 * 128; i += 256) sw[i] = W[i];
    __syncthreads();
    int sub = threadIdx.x >> 7;       // 0 or 1
    int c   = threadIdx.x & 127;
    int e0  = blockIdx.x * 16 + sub;
    for (int r = 0; r < 16; r += 2) {
        int e = e0 + r;
        if (e >= EE) return;
        float acc = 0.f;
#pragma unroll
        for (int k = 0; k < 5; k++) acc += hfeat[e * 5 + k] * sw[k * 128 + c];
        outp[e * 128 + c] = acc;
    }
}

// ------------------------- zero -------------------------
__global__ void k_zero(float* __restrict__ p, int n) {
    int i = blockIdx.x * blockDim.x + threadIdx.x;
    int str = gridDim.x * blockDim.x;
    for (; i < n; i += str) p[i] = 0.f;
}

// ------------------------- generic tiled SGEMM with fused gather -------------------------
// MODE 0 (edge update): A[e] = [he(128) | hn[src](256) | hn[dst](256) | dist(1)], K=641, Ncols=128
//                       C = relu(A@W + b) -> he_new
// MODE 1 (message):     A[e] = [hn[src](256) | he_new(128)], K=384, Ncols=256
//                       atomicAdd relu(A@W + b) into agg[dst]
// MODE 2 (node update): A[n] = [hn(256) | agg(256)], K=512, Ncols=256
//                       C = hn + relu(A@W + b)
// MODE 3 (final mlp 1): A = hsub[B,384], K=384, Ncols=512, C = relu(A@W + b)
// MODE 4 (final mlp 2): A = h1[B,512],  K=512, Ncols=256, C = A@W + b
template <int MODE>
__global__ __launch_bounds__(256) void gemm_k(
    const float* __restrict__ P0, const float* __restrict__ P1,
    const float* __restrict__ Wb, const float* __restrict__ bias,
    float* __restrict__ Cout, const float* __restrict__ Extra,
    const int* __restrict__ src, const int* __restrict__ dst,
    const float* __restrict__ distv,
    int Mrows, int Kdim, int Ncols)
{
    __shared__ __align__(16) float As[16][128];
    __shared__ __align__(16) float Bs[16][128];
    const int tid = threadIdx.x;
    const int tx = tid & 15, ty = tid >> 4;
    const int m0 = blockIdx.x * 128;
    const int n0 = blockIdx.y * 128;

    float acc[8][8];
#pragma unroll
    for (int i = 0; i < 8; i++)
#pragma unroll
        for (int j = 0; j < 8; j++) acc[i][j] = 0.f;

    const int ar  = tid & 127;
    const int ak0 = (tid >> 7) * 8;
    const int rowg = m0 + ar;
    const bool rvalid = (rowg < Mrows);
    int rs = 0, rd = 0;
    if (MODE == 0) { if (rvalid) { rs = src[rowg]; rd = dst[rowg]; } }
    if (MODE == 1) { if (rvalid) { rs = src[rowg]; } }

    const int KT = (Kdim + 15) >> 4;
    for (int kt = 0; kt < KT; kt++) {
        // ---- load A tile (gathered) ----
#pragma unroll
        for (int j = 0; j < 8; j++) {
            int k = kt * 16 + ak0 + j;
            float v = 0.f;
            if (rvalid && k < Kdim) {
                if (MODE == 0) {
                    if (k < ED)               v = P0[rowg * ED + k];
                    else if (k < ED + ND)     v = P1[rs * ND + (k - ED)];
                    else if (k < ED + 2 * ND) v = P1[rd * ND + (k - ED - ND)];
                    else                      v = distv[rowg];
                } else if (MODE == 1) {
                    if (k < ND) v = P0[rs * ND + k];
                    else        v = P1[rowg * ED + (k - ND)];
                } else if (MODE == 2) {
                    if (k < ND) v = P0[rowg * ND + k];
                    else        v = P1[rowg * ND + (k - ND)];
                } else if (MODE == 3) {
                    v = P0[rowg * 384 + k];
                } else {
                    v = P0[rowg * 512 + k];
                }
            }
            As[ak0 + j][ar] = v;
        }
        // ---- load B tile (weights, coalesced float4) ----
#pragma unroll
        for (int r = 0; r < 2; r++) {
            int f  = tid + r * 256;
            int bk = f >> 5;
            int bc = (f & 31) * 4;
            int kg = kt * 16 + bk;
            float4 v = make_float4(0.f, 0.f, 0.f, 0.f);
            if (kg < Kdim) v = *(const float4*)(Wb + (size_t)kg * Ncols + n0 + bc);
            *(float4*)&Bs[bk][bc] = v;
        }
        __syncthreads();
#pragma unroll
        for (int kk = 0; kk < 16; kk++) {
            float a[8], b[8];
            *(float4*)&a[0] = *(const float4*)&As[kk][ty * 8];
            *(float4*)&a[4] = *(const float4*)&As[kk][ty * 8 + 4];
            *(float4*)&b[0] = *(const float4*)&Bs[kk][tx * 8];
            *(float4*)&b[4] = *(const float4*)&Bs[kk][tx * 8 + 4];
#pragma unroll
            for (int i = 0; i < 8; i++)
#pragma unroll
                for (int j = 0; j < 8; j++) acc[i][j] += a[i] * b[j];
        }
        __syncthreads();
    }

    // ---- epilogue ----
#pragma unroll
    for (int i = 0; i < 8; i++) {
        int rg = m0 + ty * 8 + i;
        if (rg >= Mrows) continue;
        int dsti = 0;
        if (MODE == 1) dsti = dst[rg];
#pragma unroll
        for (int j = 0; j < 8; j++) {
            int cg = n0 + tx * 8 + j;
            float v = acc[i][j] + bias[cg];
            if (MODE == 0)      Cout[rg * ED + cg] = fmaxf(v, 0.f);
            else if (MODE == 1) atomicAdd(&Cout[dsti * ND + cg], fmaxf(v, 0.f));
            else if (MODE == 2) Cout[rg * ND + cg] = Extra[rg * ND + cg] + fmaxf(v, 0.f);
            else if (MODE == 3) Cout[rg * 512 + cg] = fmaxf(v, 0.f);
            else                Cout[rg * EMBD + cg] = v;
        }
    }
}

// ------------------------- pooling -------------------------
__global__ void k_count(const int* __restrict__ b, int n, float* __restrict__ cnt) {
    int i = blockIdx.x * 256 + threadIdx.x;
    if (i < n) atomicAdd(&cnt[b[i]], 1.f);
}

__global__ void k_pool_node(const float* __restrict__ hn) {
    int n0 = blockIdx.x * 128;
    int c = threadIdx.x;  // 256 threads
    float acc = 0.f;
    int cur = -1;
    for (int i = 0; i < 128; i++) {
        int n = n0 + i;
        if (n >= NN) break;
        int b = g_bn[n];
        if (b != cur) {
            if (cur >= 0) atomicAdd(&g_sum_n[cur * ND + c], acc);
            cur = b; acc = 0.f;
        }
        acc += hn[n * ND + c];
    }
    if (cur >= 0) atomicAdd(&g_sum_n[cur * ND + c], acc);
}

__global__ void k_pool_edge(const float* __restrict__ he) {
    int e0 = blockIdx.x * 512;
    int c = threadIdx.x;  // 128 threads
    float acc = 0.f;
    int cur = -1;
    for (int i = 0; i < 512; i++) {
        int e = e0 + i;
        if (e >= EE) break;
        int b = g_be[e];
        if (b != cur) {
            if (cur >= 0) atomicAdd(&g_sum_e[cur * ED + c], acc);
            cur = b; acc = 0.f;
        }
        acc += he[e * ED + c];
    }
    if (cur >= 0) atomicAdd(&g_sum_e[cur * ED + c], acc);
}

__global__ void k_hsub() {
    int idx = blockIdx.x * 256 + threadIdx.x;
    if (idx >= BB * (ND + ED)) return;
    int b = idx / (ND + ED);
    int c = idx % (ND + ED);
    float v;
    if (c < ND) v = g_sum_n[b * ND + c] / fmaxf(g_cnt_n[b], 1.f);
    else        v = g_sum_e[b * ED + (c - ND)] / fmaxf(g_cnt_e[b], 1.f);
    g_hsub[idx] = v;
}

__global__ void k_copy_batch(float* __restrict__ outp) {
    int i = blockIdx.x * 256 + threadIdx.x;
    if (i < NN) outp[i] = (float)g_bn[i];
}

// ------------------------- launch -------------------------
extern "C" void kernel_launch(void* const* d_in, const int* in_sizes, int n_in,
                              void* d_out, int out_size) {
    const float* h_node = (const float*)d_in[0];
    const float* pos    = (const float*)d_in[1];
    const float* h_edge = (const float*)d_in[2];
    const float* W_node = (const float*)d_in[3];
    const float* W_edge = (const float*)d_in[4];
    const float* W_eu   = (const float*)d_in[5];
    const float* b_eu   = (const float*)d_in[6];
    const float* W_msg  = (const float*)d_in[7];
    const float* b_msg  = (const float*)d_in[8];
    const float* W_nu   = (const float*)d_in[9];
    const float* b_nu   = (const float*)d_in[10];
    const float* Wf1    = (const float*)d_in[11];
    const float* bf1    = (const float*)d_in[12];
    const float* Wf2    = (const float*)d_in[13];
    const float* bf2    = (const float*)d_in[14];
    const void*  ei     = d_in[15];
    const void*  bn     = d_in[16];
    const void*  be     = d_in[17];
    float* outp = (float*)d_out;

    float *hn0, *hn1, *he0, *he1, *agg, *distp, *sumn, *sume, *cntn, *cnte, *hsub, *h1;
    int *srcp, *dstp, *bnp, *bep;
    cudaGetSymbolAddress((void**)&hn0, g_hn0);
    cudaGetSymbolAddress((void**)&hn1, g_hn1);
    cudaGetSymbolAddress((void**)&he0, g_he0);
    cudaGetSymbolAddress((void**)&he1, g_he1);
    cudaGetSymbolAddress((void**)&agg, g_agg);
    cudaGetSymbolAddress((void**)&distp, g_dist);
    cudaGetSymbolAddress((void**)&srcp, g_src);
    cudaGetSymbolAddress((void**)&dstp, g_dst);
    cudaGetSymbolAddress((void**)&bnp, g_bn);
    cudaGetSymbolAddress((void**)&bep, g_be);
    cudaGetSymbolAddress((void**)&sumn, g_sum_n);
    cudaGetSymbolAddress((void**)&sume, g_sum_e);
    cudaGetSymbolAddress((void**)&cntn, g_cnt_n);
    cudaGetSymbolAddress((void**)&cnte, g_cnt_e);
    cudaGetSymbolAddress((void**)&hsub, g_hsub);
    cudaGetSymbolAddress((void**)&h1, g_h1);

    // normalize index dtypes (JAX default disables x64 -> int32 likely)
    k_detect<<<1, 32>>>((const unsigned int*)ei);
    k_cvt<<<(EE + 255) / 256, 256>>>(ei, EE, srcp);
    k_cvt<<<(EE + 255) / 256, 256>>>((const char*)ei + 0, EE, srcp); // src = row 0
    // dst = row 1: offset depends on dtype; do it inside a dedicated kernel instead
    // (see k_cvt_dst below) -- replaced by two-stage convert:
    // NOTE: the line above is redundant (same src convert twice, harmless/deterministic)

    // dst row: offset EE elements of the detected dtype
    {
        // convert dst using a kernel that applies the element offset internally
        struct Dummy {};
    }
    // dst conversion kernel launch
    extern __global__ void k_cvt_off(const void*, int, int, int*);
    k_cvt_off<<<(EE + 255) / 256, 256>>>(ei, EE, EE, dstp);
    k_cvt<<<(NN + 255) / 256, 256>>>(bn, NN, bnp);
    k_cvt<<<(EE + 255) / 256, 256>>>(be, EE, bep);

    k_prep_edge<<<(EE + 255) / 256, 256>>>(pos);
    k_embed_node<<<NN / 8, 256>>>(h_node, W_node, hn0);
    k_embed_edge<<<EE / 16, 256>>>(h_edge, W_edge, he0);

    float *hnc = hn0, *hnn = hn1, *hec = he0, *hen = he1;
    for (int l = 0; l < LBLK; l++) {
        // edge update: he_new = relu([he | hn_src | hn_dst | dist] @ W_eu + b)
        gemm_k<0><<<dim3(EE / 128, 1), 256>>>(hec, hnc,
            W_eu + (size_t)l * 641 * 128, b_eu + l * 128,
            hen, nullptr, srcp, dstp, distp, EE, 641, 128);
        // zero agg
        k_zero<<<4096, 256>>>(agg, NN * ND);
        // messages + scatter-add
        gemm_k<1><<<dim3(EE / 128, 2), 256>>>(hnc, hen,
            W_msg + (size_t)l * 384 * 256, b_msg + l * 256,
            agg, nullptr, srcp, dstp, nullptr, EE, 384, 256);
        // node update: hn = hn + relu([hn | agg] @ W_nu + b)
        gemm_k<2><<<dim3((NN + 127) / 128, 2), 256>>>(hnc, agg,
            W_nu + (size_t)l * 512 * 256, b_nu + l * 256,
            hnn, hnc, nullptr, nullptr, nullptr, NN, 512, 256);
        { float* t = hnc; hnc = hnn; hnn = t; }
        { float* t = hec; hec = hen; hen = t; }
    }

    // pooling
    k_zero<<<256, 256>>>(sumn, BB * ND);
    k_zero<<<256, 256>>>(sume, BB * ED);
    k_zero<<<8, 256>>>(cntn, BB);
    k_zero<<<8, 256>>>(cnte, BB);
    k_count<<<(NN + 255) / 256, 256>>>(bnp, NN, cntn);
    k_count<<<(EE + 255) / 256, 256>>>(bep, EE, cnte);
    k_pool_node<<<(NN + 127) / 128, 256>>>(hnc);
    k_pool_edge<<<(EE + 511) / 512, 128>>>(hec);
    k_hsub<<<(BB * (ND + ED) + 255) / 256, 256>>>();

    // final MLP
    gemm_k<3><<<dim3((BB + 127) / 128, 4), 256>>>(hsub, nullptr, Wf1, bf1,
        h1, nullptr, nullptr, nullptr, nullptr, BB, 384, 512);
    gemm_k<4><<<dim3((BB + 127) / 128, 2), 256>>>(h1, nullptr, Wf2, bf2,
        outp, nullptr, nullptr, nullptr, nullptr, BB, 512, 256);

    // if the harness output also contains batch_node (tuple return), append it
    if (out_size >= BB * EMBD + NN) {
        k_copy_batch<<<(NN + 255) / 256, 256>>>(outp + BB * EMBD);
    }
}

// offset-aware converter (element offset in the detected dtype)
__global__ void k_cvt_off(const void* __restrict__ p, int n, int off,
                          int* __restrict__ outp) {
    int i = blockIdx.x * 256 + threadIdx.x;
    if (i >= n) return;
    if (g_is64) outp[i] = (int)((const long long*)p)[off + i];
    else        outp[i] = ((const int*)p)[off + i];
}